// round 17
// baseline (speedup 1.0000x reference)
#include <cuda_runtime.h>
#include <math.h>

typedef unsigned long long ull;
typedef unsigned int uint;

#define B_    2
#define L_    1728
#define NTOK  3456
#define C_    256
#define U_    256
#define H_    8
#define HD    32
#define FF_   1024
#define EPS_  1e-3f
#define NKT   27

#define FRELU   1
#define FRESID  2
#define FPLANES 4
#define FOUT    8
#define FSUM3   16
#define FPLHI   32
#define FX2     64
#define FVT     128

// gemmT dynamic smem: As_hi[2][64][36], As_lo[2][64][36],
//                     Ws_hi[2][128][36], Ws_lo[2][128][36]
#define ASH_W   (2*64*36)
#define WSH_W   (2*128*36)
#define GSMEM_W (2*ASH_W + 2*WSH_W)
#define GSMEM_B (GSMEM_W * 4)

// ---------------- cp.async helpers ------------------------------------------
__device__ __forceinline__ void cp16(uint saddr, const void* gptr) {
    asm volatile("cp.async.cg.shared.global [%0], [%1], 16;" :: "r"(saddr), "l"(gptr));
}
__device__ __forceinline__ uint sa(const void* p) {
    return (uint)__cvta_generic_to_shared(p);
}
#define CP_COMMIT() asm volatile("cp.async.commit_group;")
#define CP_WAIT0()  asm volatile("cp.async.wait_group 0;")
#define CP_WAIT1()  asm volatile("cp.async.wait_group 1;")

// ---------------- ldmatrix ----------------------------------------------------
__device__ __forceinline__ void ldsm4(uint& r0, uint& r1, uint& r2, uint& r3, uint saddr) {
    asm volatile("ldmatrix.sync.aligned.m8n8.x4.shared.b16 {%0,%1,%2,%3}, [%4];"
                 : "=r"(r0), "=r"(r1), "=r"(r2), "=r"(r3) : "r"(saddr));
}

// ---------------- fast exp2 --------------------------------------------------
__device__ __forceinline__ float ex2(float x) {
    float y; asm("ex2.approx.f32 %0,%1;" : "=f"(y) : "f"(x)); return y;
}

// ---------------- bf16 split helpers ---------------------------------------
__device__ __forceinline__ uint bf16_of(float f) {
    unsigned short u; asm("cvt.rn.bf16.f32 %0,%1;" : "=h"(u) : "f"(f));
    return (uint)u;
}
__device__ __forceinline__ void split_pair(float f0, float f1, uint& hi, uint& lo) {
    uint h0 = bf16_of(f0), h1 = bf16_of(f1);
    hi = h0 | (h1 << 16);
    float r0 = f0 - __uint_as_float(h0 << 16);
    float r1 = f1 - __uint_as_float(h1 << 16);
    lo = bf16_of(r0) | (bf16_of(r1) << 16);
}
__device__ __forceinline__ uint pack_hi(float f0, float f1) {
    return bf16_of(f0) | (bf16_of(f1) << 16);
}

// ---------------- mma m16n8k16 bf16 -----------------------------------------
__device__ __forceinline__ void mma_bf16(float* c, uint a0, uint a1, uint a2, uint a3,
                                         uint b0, uint b1) {
    asm volatile("mma.sync.aligned.m16n8k16.row.col.f32.bf16.bf16.f32 "
                 "{%0,%1,%2,%3},{%4,%5,%6,%7},{%8,%9},{%0,%1,%2,%3};"
                 : "+f"(c[0]), "+f"(c[1]), "+f"(c[2]), "+f"(c[3])
                 : "r"(a0), "r"(a1), "r"(a2), "r"(a3), "r"(b0), "r"(b1));
}

// ---------------- scratch ---------------------------------------------------
__device__ float d_h   [NTOK*U_];
__device__ float d_O1  [NTOK*U_];
__device__ float d_O2  [NTOK*U_];

__device__ uint d_xhi [NTOK*128], d_xlo [NTOK*128];
__device__ uint d_cthi[NTOK*128], d_ctlo[NTOK*128];
__device__ uint d_hhi [NTOK*128], d_hlo [NTOK*128];
__device__ uint d_nhi [NTOK*128], d_nlo [NTOK*128];
__device__ uint d_f1hi[NTOK*512];
__device__ uint d_ahi [NTOK*128], d_alo [NTOK*128];
__device__ uint d_q1hi[NTOK*128];
__device__ uint d_k1hi[NTOK*128];
__device__ uint d_q2hi[NTOK*128];
__device__ uint d_k2hi[NTOK*128];
__device__ uint d_vthi[32*32*864];

__device__ uint d_Wpin_h[256*128], d_Wpin_l[256*128];
__device__ uint d_Wq1_h [256*128], d_Wq1_l [256*128];
__device__ uint d_Wq2_h [256*128], d_Wq2_l [256*128];
__device__ uint d_Wk_h  [256*128], d_Wk_l  [256*128];
__device__ uint d_Wv_h  [256*128], d_Wv_l  [256*128];
__device__ uint d_Wpout_h[256*128], d_Wpout_l[256*128];
__device__ uint d_Wff1_h[1024*128], d_Wff1_l[1024*128];
__device__ uint d_Wff2_h[256*512],  d_Wff2_l[256*512];

__device__ float d_bpin[U_], d_bq1[U_], d_bq2[U_], d_bff1[FF_];

// ---------------- prep_all (one launch) --------------------------------------
__global__ void __launch_bounds__(256) prep_all(
    const float* __restrict__ x,    const float* __restrict__ ctx,
    const float* __restrict__ bn_g, const float* __restrict__ bn_b,
    const float* __restrict__ bn_m, const float* __restrict__ bn_v,
    const float* __restrict__ ln1_g, const float* __restrict__ ln1_b,
    const float* __restrict__ ln2_g, const float* __restrict__ ln2_b,
    const float* __restrict__ ln3_g, const float* __restrict__ ln3_b,
    const float* __restrict__ pin_w, const float* __restrict__ pin_b,
    const float* __restrict__ q_w,  const float* __restrict__ q_b,
    const float* __restrict__ k_w,  const float* __restrict__ v_w,
    const float* __restrict__ ff1_w, const float* __restrict__ ff1_b,
    const float* __restrict__ ff2_w, const float* __restrict__ pout_w)
{
    int blk = blockIdx.x;
    int tid = threadIdx.x;

    if (blk < 1792) {
        int w = blk * 256 + tid;
        float w0, w1;
        uint *dh, *dl;
        size_t oidx;
        if (w < 196608) {
            int r = w >> 15;
            int idx = w & 32767;
            int u = idx >> 7, k2 = idx & 127;
            int k = k2 * 2;
            oidx = (size_t)u * 128 + k2;
            switch (r) {
            case 0: {
                float s0 = rsqrtf(bn_v[k] + EPS_) * bn_g[k];
                float s1 = rsqrtf(bn_v[k+1] + EPS_) * bn_g[k+1];
                w0 = s0 * pin_w[k*256 + u]; w1 = s1 * pin_w[(k+1)*256 + u];
                dh = d_Wpin_h; dl = d_Wpin_l; } break;
            case 1:
                w0 = ln1_g[k] * q_w[k*256 + u]; w1 = ln1_g[k+1] * q_w[(k+1)*256 + u];
                dh = d_Wq1_h; dl = d_Wq1_l; break;
            case 2:
                w0 = ln2_g[k] * q_w[k*256 + u]; w1 = ln2_g[k+1] * q_w[(k+1)*256 + u];
                dh = d_Wq2_h; dl = d_Wq2_l; break;
            case 3:
                w0 = k_w[k*256 + u]; w1 = k_w[(k+1)*256 + u];
                dh = d_Wk_h; dl = d_Wk_l; break;
            case 4:
                w0 = v_w[k*256 + u]; w1 = v_w[(k+1)*256 + u];
                dh = d_Wv_h; dl = d_Wv_l; break;
            default:
                w0 = pout_w[k*256 + u]; w1 = pout_w[(k+1)*256 + u];
                dh = d_Wpout_h; dl = d_Wpout_l; break;
            }
        } else if (w < 327680) {
            int idx = w - 196608;
            int u = idx >> 7, k2 = idx & 127;
            int k = k2 * 2;
            oidx = (size_t)u * 128 + k2;
            w0 = ln3_g[k] * ff1_w[k*1024 + u]; w1 = ln3_g[k+1] * ff1_w[(k+1)*1024 + u];
            dh = d_Wff1_h; dl = d_Wff1_l;
        } else {
            int idx = w - 327680;
            int u = idx >> 9, k2 = idx & 511;
            int k = k2 * 2;
            oidx = (size_t)u * 512 + k2;
            w0 = ff2_w[k*256 + u]; w1 = ff2_w[(k+1)*256 + u];
            dh = d_Wff2_h; dl = d_Wff2_l;
        }
        uint hi, lo; split_pair(w0, w1, hi, lo);
        dh[oidx] = hi; dl[oidx] = lo;
    } else if (blk < 5248) {
        int rel = blk - 1792;
        const float* s; uint *ph, *pl;
        if (rel < 1728) { s = x; ph = d_xhi; pl = d_xlo; }
        else { rel -= 1728; s = ctx; ph = d_cthi; pl = d_ctlo; }
        int i = rel * 256 + tid;
        float2 f = ((const float2*)s)[i];
        uint h, l; split_pair(f.x, f.y, h, l);
        ph[i] = h; pl[i] = l;
    } else {
        int gw = (blk - 5248) * 8 + (tid >> 5);
        int lane = tid & 31;
        float part = 0.f;
        int u;
        if (gw < 256) {
            u = gw;
            for (int k = lane; k < 256; k += 32) {
                float sc = rsqrtf(bn_v[k] + EPS_) * bn_g[k];
                part += (bn_b[k] - bn_m[k] * sc) * pin_w[k*256 + u];
            }
        } else if (gw < 512) {
            u = gw - 256;
            for (int k = lane; k < 256; k += 32) part += ln1_b[k] * q_w[k*256 + u];
        } else if (gw < 768) {
            u = gw - 512;
            for (int k = lane; k < 256; k += 32) part += ln2_b[k] * q_w[k*256 + u];
        } else {
            u = gw - 768;
            for (int k = lane; k < 256; k += 32) part += ln3_b[k] * ff1_w[k*1024 + u];
        }
        #pragma unroll
        for (int o = 16; o > 0; o >>= 1) part += __shfl_xor_sync(0xffffffffu, part, o);
        if (lane == 0) {
            if (gw < 256)      d_bpin[u] = pin_b[u] + part;
            else if (gw < 512) d_bq1[u]  = q_b[u]  + part;
            else if (gw < 768) d_bq2[u]  = q_b[u]  + part;
            else               d_bff1[u] = ff1_b[u] + part;
        }
    }
}

// ---------------- tensor-core batched GEMM: 64x128, K64 stages, ldmatrix ----
struct GOp {
    const uint* Ahi; const uint* Alo;
    const uint* Whi; const uint* Wlo;
    const float* bias; const float* resid;
    const float* sum1; const float* sum2; const float* sum3;
    float* out; uint* Ohi; uint* Olo;
    uint* vt; int vbr;
    int N; int K; int flags; int tileStart;
};
struct GBatch { GOp op[8]; int nops; };

__global__ void __launch_bounds__(256, 2) gemmT(GBatch P)
{
    extern __shared__ __align__(16) uint smem_u[];
    uint* AsH = smem_u;                 // [2][64][36]
    uint* AsL = AsH + ASH_W;            // [2][64][36]
    uint* WsH = AsL + ASH_W;            // [2][128][36]
    uint* WsL = WsH + WSH_W;            // [2][128][36]
#define ASHp(s,r,w) (AsH + (s)*2304 + (r)*36 + (w))
#define ASLp(s,r,w) (AsL + (s)*2304 + (r)*36 + (w))
#define WSHp(s,r,w) (WsH + (s)*4608 + (r)*36 + (w))
#define WSLp(s,r,w) (WsL + (s)*4608 + (r)*36 + (w))

    int bid = blockIdx.x;
    int sel = 0;
    #pragma unroll
    for (int i = 1; i < 8; i++)
        if (i < P.nops && bid >= P.op[i].tileStart) sel = i;
    GOp g = P.op[sel];
    bool x2 = (g.flags & FX2) != 0;

    int local = bid - g.tileStart;
    int ntn = g.N >> 7;
    int mt = local / ntn;
    int nt = local - mt * ntn;
    int m0 = mt * 64, n0 = nt * 128;
    int tid = threadIdx.x;
    int warp = tid >> 5, lane = tid & 31;
    int gq = lane >> 2, t = lane & 3;
    int rw = warp & 3;
    int ch = warp >> 2;
    int K2 = g.K >> 1;

    int lrow = lane & 7, lm = lane >> 3;

    float acc[8][4];
    #pragma unroll
    for (int j = 0; j < 8; j++)
        #pragma unroll
        for (int i = 0; i < 4; i++) acc[j][i] = 0.f;

    // fill indices: stage = K64 = 32 words/row
    int arow = tid >> 2;                // 0..63
    int awo  = (tid & 3) * 8;           // 0,8,16,24
    int wrow = tid >> 1;                // 0..127
    int wwo  = (tid & 1) * 16;          // 0,16
    const size_t abase = (size_t)(m0 + arow) * K2 + awo;
    const size_t wbase = (size_t)(n0 + wrow) * K2 + wwo;

    int nst = K2 >> 5;                  // K64 stages

    {   // prefetch stage 0
        cp16(sa(ASHp(0, arow, awo)),     g.Ahi + abase);
        cp16(sa(ASHp(0, arow, awo + 4)), g.Ahi + abase + 4);
        if (!x2) {
            cp16(sa(ASLp(0, arow, awo)),     g.Alo + abase);
            cp16(sa(ASLp(0, arow, awo + 4)), g.Alo + abase + 4);
        }
        #pragma unroll
        for (int q = 0; q < 4; q++) {
            cp16(sa(WSHp(0, wrow, wwo + q*4)), g.Whi + wbase + q*4);
            cp16(sa(WSLp(0, wrow, wwo + q*4)), g.Wlo + wbase + q*4);
        }
        CP_COMMIT();
    }

    int a_r = (rw << 4) + ((lm & 1) << 3) + lrow;
    int a_w = (lm >> 1) << 2;
    int b_rbase = (ch << 6) + ((lm >> 1) << 3) + lrow;
    int b_w = (lm & 1) << 2;

    for (int c = 0; c < nst; c++) {
        CP_WAIT0();
        __syncthreads();
        int pc = c + 1;
        if (pc < nst) {
            int nb = pc & 1;
            size_t off = (size_t)pc * 32;
            cp16(sa(ASHp(nb, arow, awo)),     g.Ahi + abase + off);
            cp16(sa(ASHp(nb, arow, awo + 4)), g.Ahi + abase + off + 4);
            if (!x2) {
                cp16(sa(ASLp(nb, arow, awo)),     g.Alo + abase + off);
                cp16(sa(ASLp(nb, arow, awo + 4)), g.Alo + abase + off + 4);
            }
            #pragma unroll
            for (int q = 0; q < 4; q++) {
                cp16(sa(WSHp(nb, wrow, wwo + q*4)), g.Whi + wbase + off + q*4);
                cp16(sa(WSLp(nb, wrow, wwo + q*4)), g.Wlo + wbase + off + q*4);
            }
        }
        CP_COMMIT();

        int bb = c & 1;
        #pragma unroll
        for (int hf = 0; hf < 4; hf++) {
            int wo = hf * 8;
            uint a0h, a1h, a2h, a3h;
            ldsm4(a0h, a1h, a2h, a3h, sa(ASHp(bb, a_r, a_w + wo)));
            uint a0l = 0, a1l = 0, a2l = 0, a3l = 0;
            if (!x2) ldsm4(a0l, a1l, a2l, a3l, sa(ASLp(bb, a_r, a_w + wo)));

            #pragma unroll
            for (int jp = 0; jp < 4; jp++) {
                uint bh0, bh1, bh2, bh3, bl0, bl1, bl2, bl3;
                ldsm4(bh0, bh1, bh2, bh3, sa(WSHp(bb, b_rbase + jp*16, b_w + wo)));
                ldsm4(bl0, bl1, bl2, bl3, sa(WSLp(bb, b_rbase + jp*16, b_w + wo)));
                mma_bf16(acc[jp*2  ], a0h, a1h, a2h, a3h, bh0, bh1);
                mma_bf16(acc[jp*2  ], a0h, a1h, a2h, a3h, bl0, bl1);
                mma_bf16(acc[jp*2+1], a0h, a1h, a2h, a3h, bh2, bh3);
                mma_bf16(acc[jp*2+1], a0h, a1h, a2h, a3h, bl2, bl3);
                if (!x2) {
                    mma_bf16(acc[jp*2  ], a0l, a1l, a2l, a3l, bh0, bh1);
                    mma_bf16(acc[jp*2+1], a0l, a1l, a2l, a3l, bh2, bh3);
                }
            }
        }
    }

    int K2o = g.N >> 1;
    int r0 = m0 + rw*16 + gq;
    int r1 = r0 + 8;
    #pragma unroll
    for (int j = 0; j < 8; j++) {
        int c0 = n0 + ch*64 + j*8 + 2*t;
        float b0 = g.bias[c0], b1 = g.bias[c0+1];
        float v00 = acc[j][0] + b0, v01 = acc[j][1] + b1;
        float v10 = acc[j][2] + b0, v11 = acc[j][3] + b1;
        if (g.flags & FRELU) {
            v00 = fmaxf(v00, 0.f); v01 = fmaxf(v01, 0.f);
            v10 = fmaxf(v10, 0.f); v11 = fmaxf(v11, 0.f);
        }
        if (g.flags & FRESID) {
            float2 ra = *(const float2*)&g.resid[(size_t)r0*g.N + c0];
            float2 rb = *(const float2*)&g.resid[(size_t)r1*g.N + c0];
            v00 += ra.x; v01 += ra.y; v10 += rb.x; v11 += rb.y;
        }
        if (g.flags & FSUM3) {
            float2 a1 = *(const float2*)&g.sum1[(size_t)r0*g.N + c0];
            float2 a2 = *(const float2*)&g.sum2[(size_t)r0*g.N + c0];
            float2 a3 = *(const float2*)&g.sum3[(size_t)r0*g.N + c0];
            v00 += a1.x + a2.x + a3.x; v01 += a1.y + a2.y + a3.y;
            float2 c1 = *(const float2*)&g.sum1[(size_t)r1*g.N + c0];
            float2 c2 = *(const float2*)&g.sum2[(size_t)r1*g.N + c0];
            float2 c3 = *(const float2*)&g.sum3[(size_t)r1*g.N + c0];
            v10 += c1.x + c2.x + c3.x; v11 += c1.y + c2.y + c3.y;
        }
        if (g.flags & FVT) {
            float p00 = __shfl_xor_sync(0xffffffffu, v00, 4);
            float p01 = __shfl_xor_sync(0xffffffffu, v01, 4);
            float p10 = __shfl_xor_sync(0xffffffffu, v10, 4);
            float p11 = __shfl_xor_sync(0xffffffffu, v11, 4);
            if (!(gq & 1)) {
                int bidx = r0 / L_;
                int key0 = r0 - bidx * L_;
                int head = c0 >> 5, d = c0 & 31;
                int gg = (g.vbr * 2 + bidx) * 8 + head;
                size_t base = ((size_t)gg * 32 + d) * 864;
                g.vt[base + (key0 >> 1)]       = pack_hi(v00, p00);
                g.vt[base + 864 + (key0 >> 1)] = pack_hi(v01, p01);
                int kp1 = (key0 >> 1) + 4;
                g.vt[base + kp1]       = pack_hi(v10, p10);
                g.vt[base + 864 + kp1] = pack_hi(v11, p11);
            }
        }
        if (g.flags & FOUT) {
            *(float2*)&g.out[(size_t)r0*g.N + c0] = make_float2(v00, v01);
            *(float2*)&g.out[(size_t)r1*g.N + c0] = make_float2(v10, v11);
        }
        if (g.flags & FPLANES) {
            uint h, l;
            split_pair(v00, v01, h, l);
            g.Ohi[(size_t)r0*K2o + (c0>>1)] = h; g.Olo[(size_t)r0*K2o + (c0>>1)] = l;
            split_pair(v10, v11, h, l);
            g.Ohi[(size_t)r1*K2o + (c0>>1)] = h; g.Olo[(size_t)r1*K2o + (c0>>1)] = l;
        } else if (g.flags & FPLHI) {
            g.Ohi[(size_t)r0*K2o + (c0>>1)] = pack_hi(v00, v01);
            g.Ohi[(size_t)r1*K2o + (c0>>1)] = pack_hi(v10, v11);
        }
    }
#undef ASHp
#undef ASLp
#undef WSHp
#undef WSLp
}

// ---------------- LayerNorm -> planes ----------------------------------------
__global__ void __launch_bounds__(256) lnorm_kernel(const float* __restrict__ h,
                                                    uint* __restrict__ nhi,
                                                    uint* __restrict__ nlo)
{
    int row = blockIdx.x;
    int tid = threadIdx.x;
    float v = h[(size_t)row * 256 + tid];
    __shared__ float red[8];
    float s = v;
    #pragma unroll
    for (int o = 16; o > 0; o >>= 1) s += __shfl_xor_sync(0xffffffffu, s, o);
    if ((tid & 31) == 0) red[tid >> 5] = s;
    __syncthreads();
    float tot = 0.f;
    #pragma unroll
    for (int i = 0; i < 8; i++) tot += red[i];
    float mu = tot * (1.f / 256.f);
    float d = v - mu;
    float s2 = d * d;
    #pragma unroll
    for (int o = 16; o > 0; o >>= 1) s2 += __shfl_xor_sync(0xffffffffu, s2, o);
    __syncthreads();
    if ((tid & 31) == 0) red[tid >> 5] = s2;
    __syncthreads();
    float tot2 = 0.f;
    #pragma unroll
    for (int i = 0; i < 8; i++) tot2 += red[i];
    float var = tot2 * (1.f / 256.f);
    float o = d * rsqrtf(var + EPS_);
    float pn = __shfl_xor_sync(0xffffffffu, o, 1);
    if (!(tid & 1)) {
        uint hi, lo; split_pair(o, pn, hi, lo);
        nhi[(size_t)row * 128 + (tid >> 1)] = hi;
        nlo[(size_t)row * 128 + (tid >> 1)] = lo;
    }
}

// ---------------- tensor-core flash attention (QK x1, PV x1, static max) ----
__global__ void __launch_bounds__(128) attn_mma(
    const uint* __restrict__ Q1hi, const uint* __restrict__ K1hi,
    const uint* __restrict__ Q2hi, const uint* __restrict__ K2hi,
    const uint* __restrict__ VThi,
    float* __restrict__ O1, float* __restrict__ O2)
{
    __shared__ __align__(16) uint Khi[3][64][20];
    __shared__ __align__(16) uint Vhi[3][32][36];

    int tid = threadIdx.x, warp = tid >> 5, lane = tid & 31;
    int gq = lane >> 2, t = lane & 3;
    int lrow = lane & 7, lm = lane >> 3;
    int qt = blockIdx.x, head = blockIdx.y;
    int br = blockIdx.z >> 1, b = blockIdx.z & 1;
    const uint* Qhi = br ? Q2hi : Q1hi;
    const uint* KhG = br ? K2hi : K1hi;
    float* Ob = br ? O2 : O1;
    const float scale2 = 0.0625f * 1.44269504089f;
    const float MSTAT  = 12.0f;

    int vg = (br * 2 + b) * 8 + head;

    int fkey = tid >> 1;
    int fkw  = (tid & 1) * 8;
    int fd   = tid >> 2;
    int fvw  = (tid & 3) * 8;
    const size_t kbase = (size_t)(b * L_ + fkey) * 128 + head * 16 + fkw;
    const size_t vbase = ((size_t)vg * 32 + fd) * 864 + fvw;

    #pragma unroll
    for (int s = 0; s < 2; s++) {
        size_t ko = kbase + (size_t)s * 64 * 128;
        size_t vo = vbase + (size_t)s * 32;
        cp16(sa(&Khi[s][fkey][fkw]),   KhG + ko);
        cp16(sa(&Khi[s][fkey][fkw+4]), KhG + ko + 4);
        cp16(sa(&Vhi[s][fd][fvw]),     VThi + vo);
        cp16(sa(&Vhi[s][fd][fvw+4]),   VThi + vo + 4);
        CP_COMMIT();
    }

    int r0 = qt * 64 + warp * 16 + gq;
    int r1 = r0 + 8;

    uint qh[2][4];
    {
        size_t q0 = (size_t)(b * L_ + r0) * 128 + head * 16;
        size_t q1 = (size_t)(b * L_ + r1) * 128 + head * 16;
        #pragma unroll
        for (int ks = 0; ks < 2; ks++) {
            qh[ks][0] = Qhi[q0 + ks*8 + t];     qh[ks][1] = Qhi[q1 + ks*8 + t];
            qh[ks][2] = Qhi[q0 + ks*8 + t + 4]; qh[ks][3] = Qhi[q1 + ks*8 + t + 4];
        }
    }

    float Oacc[4][4];
    #pragma unroll
    for (int j = 0; j < 4; j++)
        #pragma unroll
        for (int i = 0; i < 4; i++) Oacc[j][i] = 0.f;
    float l0r = 0.f, l1r = 0.f;

    int klw = lm << 2;

    for (int kt = 0; kt < NKT; kt++) {
        CP_WAIT1();
        __syncthreads();
        int pt = kt + 2;
        if (pt < NKT) {
            int nb = pt % 3;
            size_t ko = kbase + (size_t)pt * 64 * 128;
            size_t vo = vbase + (size_t)pt * 32;
            cp16(sa(&Khi[nb][fkey][fkw]),   KhG + ko);
            cp16(sa(&Khi[nb][fkey][fkw+4]), KhG + ko + 4);
            cp16(sa(&Vhi[nb][fd][fvw]),     VThi + vo);
            cp16(sa(&Vhi[nb][fd][fvw+4]),   VThi + vo + 4);
        }
        CP_COMMIT();
        int bb = kt % 3;

        float s[8][4];
        #pragma unroll
        for (int j = 0; j < 8; j++) {
            s[j][0] = s[j][1] = s[j][2] = s[j][3] = 0.f;
            uint kh0, kh1, kh2, kh3;
            ldsm4(kh0, kh1, kh2, kh3, sa(&Khi[bb][j*8 + lrow][klw]));
            mma_bf16(s[j], qh[0][0], qh[0][1], qh[0][2], qh[0][3], kh0, kh1);
            mma_bf16(s[j], qh[1][0], qh[1][1], qh[1][2], qh[1][3], kh2, kh3);
            s[j][0] = ex2(fmaf(s[j][0], scale2, -MSTAT)); l0r += s[j][0];
            s[j][1] = ex2(fmaf(s[j][1], scale2, -MSTAT)); l0r += s[j][1];
            s[j][2] = ex2(fmaf(s[j][2], scale2, -MSTAT)); l1r += s[j][2];
            s[j][3] = ex2(fmaf(s[j][3], scale2, -MSTAT)); l1r += s[j][3];
        }

        uint ph[4][4];
        #pragma unroll
        for (int ks = 0; ks < 4; ks++) {
            ph[ks][0] = pack_hi(s[2*ks  ][0], s[2*ks  ][1]);
            ph[ks][1] = pack_hi(s[2*ks  ][2], s[2*ks  ][3]);
            ph[ks][2] = pack_hi(s[2*ks+1][0], s[2*ks+1][1]);
            ph[ks][3] = pack_hi(s[2*ks+1][2], s[2*ks+1][3]);
        }

        #pragma unroll
        for (int jn = 0; jn < 4; jn++) {
            #pragma unroll
            for (int h2 = 0; h2 < 2; h2++) {
                uint vh0, vh1, vh2, vh3;
                ldsm4(vh0, vh1, vh2, vh3, sa(&Vhi[bb][jn*8 + lrow][(h2<<4) + klw]));
                int ka = 2*h2, kb2 = 2*h2 + 1;
                mma_bf16(Oacc[jn], ph[ka][0], ph[ka][1], ph[ka][2], ph[ka][3], vh0, vh1);
                mma_bf16(Oacc[jn], ph[kb2][0], ph[kb2][1], ph[kb2][2], ph[kb2][3], vh2, vh3);
            }
        }
    }

    l0r += __shfl_xor_sync(0xffffffffu, l0r, 1);
    l0r += __shfl_xor_sync(0xffffffffu, l0r, 2);
    l1r += __shfl_xor_sync(0xffffffffu, l1r, 1);
    l1r += __shfl_xor_sync(0xffffffffu, l1r, 2);

    float inv0 = 1.f / l0r, inv1 = 1.f / l1r;
    #pragma unroll
    for (int jn = 0; jn < 4; jn++) {
        int col = head * 32 + jn * 8 + 2 * t;
        *(float2*)&Ob[(size_t)(b * L_ + r0) * 256 + col] =
            make_float2(Oacc[jn][0] * inv0, Oacc[jn][1] * inv0);
        *(float2*)&Ob[(size_t)(b * L_ + r1) * 256 + col] =
            make_float2(Oacc[jn][2] * inv1, Oacc[jn][3] * inv1);
    }
}

// ---------------- launch --------------------------------------------------------
extern "C" void kernel_launch(void* const* d_in, const int* in_sizes, int n_in,
                              void* d_out, int out_size)
{
    const float* x       = (const float*)d_in[0];
    const float* context = (const float*)d_in[1];
    const float* bn_g = (const float*)d_in[2];
    const float* bn_b = (const float*)d_in[3];
    const float* bn_m = (const float*)d_in[4];
    const float* bn_v = (const float*)d_in[5];
    const float* ln1_g = (const float*)d_in[6];
    const float* ln1_b = (const float*)d_in[7];
    const float* ln2_g = (const float*)d_in[8];
    const float* ln2_b = (const float*)d_in[9];
    const float* ln3_g = (const float*)d_in[10];
    const float* ln3_b = (const float*)d_in[11];
    const float* pin_w = (const float*)d_in[12];
    const float* pin_b = (const float*)d_in[13];
    const float* q_w   = (const float*)d_in[14];
    const float* q_b   = (const float*)d_in[15];
    const float* k_w   = (const float*)d_in[16];
    const float* k_b   = (const float*)d_in[17];
    const float* v_w   = (const float*)d_in[18];
    const float* v_b   = (const float*)d_in[19];
    const float* ff1_w = (const float*)d_in[20];
    const float* ff1_b = (const float*)d_in[21];
    const float* ff2_w = (const float*)d_in[22];
    const float* ff2_b = (const float*)d_in[23];
    const float* pout_w = (const float*)d_in[24];
    const float* pout_b = (const float*)d_in[25];
    float* out = (float*)d_out;

    static bool attr_set = false;
    if (!attr_set) {
        cudaFuncSetAttribute(gemmT, cudaFuncAttributeMaxDynamicSharedMemorySize, GSMEM_B);
        attr_set = true;
    }

    float *p_h, *p_O1, *p_O2;
    uint *p_xhi, *p_xlo, *p_cthi, *p_ctlo, *p_hhi, *p_hlo, *p_nhi, *p_nlo;
    uint *p_f1hi, *p_ahi, *p_alo;
    uint *p_q1hi, *p_k1hi, *p_q2hi, *p_k2hi;
    uint *p_vthi;
    uint *w_pin_h, *w_pin_l, *w_q1_h, *w_q1_l, *w_q2_h, *w_q2_l;
    uint *w_k_h, *w_k_l, *w_v_h, *w_v_l, *w_po_h, *w_po_l;
    uint *w_f1_h, *w_f1_l, *w_f2_h, *w_f2_l;
    float *p_bpin, *p_bq1, *p_bq2, *p_bff1;

    cudaGetSymbolAddress((void**)&p_h,    d_h);
    cudaGetSymbolAddress((void**)&p_O1,   d_O1);
    cudaGetSymbolAddress((void**)&p_O2,   d_O2);
    cudaGetSymbolAddress((void**)&p_xhi,  d_xhi);
    cudaGetSymbolAddress((void**)&p_xlo,  d_xlo);
    cudaGetSymbolAddress((void**)&p_cthi, d_cthi);
    cudaGetSymbolAddress((void**)&p_ctlo, d_ctlo);
    cudaGetSymbolAddress((void**)&p_hhi,  d_hhi);
    cudaGetSymbolAddress((void**)&p_hlo,  d_hlo);
    cudaGetSymbolAddress((void**)&p_nhi,  d_nhi);
    cudaGetSymbolAddress((void**)&p_nlo,  d_nlo);
    cudaGetSymbolAddress((void**)&p_f1hi, d_f1hi);
    cudaGetSymbolAddress((void**)&p_ahi,  d_ahi);
    cudaGetSymbolAddress((void**)&p_alo,  d_alo);
    cudaGetSymbolAddress((void**)&p_q1hi, d_q1hi);
    cudaGetSymbolAddress((void**)&p_k1hi, d_k1hi);
    cudaGetSymbolAddress((void**)&p_q2hi, d_q2hi);
    cudaGetSymbolAddress((void**)&p_k2hi, d_k2hi);
    cudaGetSymbolAddress((void**)&p_vthi, d_vthi);
    cudaGetSymbolAddress((void**)&w_pin_h, d_Wpin_h);
    cudaGetSymbolAddress((void**)&w_pin_l, d_Wpin_l);
    cudaGetSymbolAddress((void**)&w_q1_h,  d_Wq1_h);
    cudaGetSymbolAddress((void**)&w_q1_l,  d_Wq1_l);
    cudaGetSymbolAddress((void**)&w_q2_h,  d_Wq2_h);
    cudaGetSymbolAddress((void**)&w_q2_l,  d_Wq2_l);
    cudaGetSymbolAddress((void**)&w_k_h,   d_Wk_h);
    cudaGetSymbolAddress((void**)&w_k_l,   d_Wk_l);
    cudaGetSymbolAddress((void**)&w_v_h,   d_Wv_h);
    cudaGetSymbolAddress((void**)&w_v_l,   d_Wv_l);
    cudaGetSymbolAddress((void**)&w_po_h,  d_Wpout_h);
    cudaGetSymbolAddress((void**)&w_po_l,  d_Wpout_l);
    cudaGetSymbolAddress((void**)&w_f1_h,  d_Wff1_h);
    cudaGetSymbolAddress((void**)&w_f1_l,  d_Wff1_l);
    cudaGetSymbolAddress((void**)&w_f2_h,  d_Wff2_h);
    cudaGetSymbolAddress((void**)&w_f2_l,  d_Wff2_l);
    cudaGetSymbolAddress((void**)&p_bpin,  d_bpin);
    cudaGetSymbolAddress((void**)&p_bq1,   d_bq1);
    cudaGetSymbolAddress((void**)&p_bq2,   d_bq2);
    cudaGetSymbolAddress((void**)&p_bff1,  d_bff1);

    // 1. all prep
    prep_all<<<5472, 256>>>(x, context, bn_g, bn_b, bn_m, bn_v,
                            ln1_g, ln1_b, ln2_g, ln2_b, ln3_g, ln3_b,
                            pin_w, pin_b, q_w, q_b, k_w, v_w,
                            ff1_w, ff1_b, ff2_w, pout_w);

    auto mkop = [](const uint* Ahi, const uint* Alo, const uint* Whi, const uint* Wlo,
                   const float* bias, const float* resid, float* o,
                   uint* Ohi, uint* Olo, int N, int K, int flags, int start) {
        GOp g = {};
        g.Ahi = Ahi; g.Alo = Alo; g.Whi = Whi; g.Wlo = Wlo;
        g.bias = bias; g.resid = resid; g.out = o; g.Ohi = Ohi; g.Olo = Olo;
        g.N = N; g.K = K; g.flags = flags; g.tileStart = start;
        return g;
    };
    const int RT = NTOK / 64;
    const int T256 = RT * 2;

    // 2. batch A: pin only (critical path to lnorm)
    {
        GBatch P = {};
        P.op[0] = mkop(p_xhi, p_xlo, w_pin_h, w_pin_l, p_bpin, nullptr,
                       p_h, p_hhi, p_hlo, 256, 256, FOUT | FRELU | FPLANES, 0);
        P.nops = 1;
        gemmT<<<T256, 256, GSMEM_B>>>(P);
    }

    // 3. hhat planes
    lnorm_kernel<<<NTOK, 256>>>(p_h, p_nhi, p_nlo);

    // 4. batch B: q1, k1, v1, q2, k2, v2, ff1
    {
        GBatch P = {};
        P.op[0] = mkop(p_nhi, nullptr, w_q1_h, w_q1_l, p_bq1, nullptr,
                       nullptr, p_q1hi, nullptr, 256, 256, FPLHI | FX2, 0);
        P.op[1] = mkop(p_hhi, nullptr, w_k_h, w_k_l, k_b, nullptr,
                       nullptr, p_k1hi, nullptr, 256, 256, FPLHI | FX2, T256);
        P.op[2] = mkop(p_hhi, nullptr, w_v_h, w_v_l, v_b, nullptr,
                       nullptr, nullptr, nullptr, 256, 256, FVT | FX2, T256*2);
        P.op[2].vt = p_vthi; P.op[2].vbr = 0;
        P.op[3] = mkop(p_nhi, nullptr, w_q2_h, w_q2_l, p_bq2, nullptr,
                       nullptr, p_q2hi, nullptr, 256, 256, FPLHI | FX2, T256*3);
        P.op[4] = mkop(p_cthi, nullptr, w_k_h, w_k_l, k_b, nullptr,
                       nullptr, p_k2hi, nullptr, 256, 256, FPLHI | FX2, T256*4);
        P.op[5] = mkop(p_cthi, nullptr, w_v_h, w_v_l, v_b, nullptr,
                       nullptr, nullptr, nullptr, 256, 256, FVT | FX2, T256*5);
        P.op[5].vt = p_vthi; P.op[5].vbr = 1;
        P.op[6] = mkop(p_nhi, p_nlo, w_f1_h, w_f1_l, p_bff1, nullptr,
                       nullptr, p_f1hi, nullptr, 1024, 256, FRELU | FPLHI, T256*6);
        P.nops = 7;
        gemmT<<<T256*6 + RT*8, 256, GSMEM_B>>>(P);   // 648 + 432 = 1080
    }

    // 5. attention (QK x1, PV x1)
    {
        dim3 ga(NKT, H_, 4);
        attn_mma<<<ga, 128>>>(p_q1hi, p_k1hi, p_q2hi, p_k2hi,
                              p_vthi, p_O1, p_O2);
    }

    // 6. ff2 (x2) + combine fused
    {
        GBatch P = {};
        P.op[0] = mkop(p_f1hi, nullptr, w_f2_h, w_f2_l, ff2_b, nullptr,
                       nullptr, p_ahi, p_alo, 256, 1024, FSUM3 | FPLANES | FX2, 0);
        P.op[0].sum1 = p_h;
        P.op[0].sum2 = p_O1;
        P.op[0].sum3 = p_O2;
        P.nops = 1;
        gemmT<<<T256, 256, GSMEM_B>>>(P);
    }

    // 7. out = relu(acc @ pout + b) + x
    {
        GBatch P = {};
        P.op[0] = mkop(p_ahi, p_alo, w_po_h, w_po_l, pout_b, x,
                       out, nullptr, nullptr, 256, 256, FOUT | FRELU | FRESID, 0);
        P.nops = 1;
        gemmT<<<T256, 256, GSMEM_B>>>(P);
    }
}